// round 8
// baseline (speedup 1.0000x reference)
#include <cuda_runtime.h>
#include <stdint.h>

#define BB 128
#define TT 1024
#define DD 256
#define UU 48

// Scratch (allocation-free rule: __device__ globals)
__device__ float         g_logits[(size_t)BB * TT * UU];     // 25.2 MB
__device__ float         g_st[(size_t)(TT - 1) * BB * UU];   // 25.1 MB (states t=0..1022)
__device__ unsigned char g_bp[(size_t)(TT - 1) * BB * UU];   // 6.29 MB
__device__ int           g_last[BB];

#define ADD_F32X2(out, a, b) \
    asm("add.rn.f32x2 %0, %1, %2;" : "=l"(out) : "l"(a), "l"(b))

// ---------------------------------------------------------------------------
// Kernel 1: logits = x @ kernel + bias (measured 105.5us ~ 1.12x fp32 floor)
// ---------------------------------------------------------------------------
#define GR 128
#define GK 64
#define XPAD 130

__global__ __launch_bounds__(128) void gemm_kernel(const float* __restrict__ x,
                                                   const float* __restrict__ w,
                                                   const float* __restrict__ bias) {
    __shared__ float xs[GK][XPAD];
    __shared__ float ws[GK][UU];

    const int tid = threadIdx.x;
    const int tc  = tid & 3;
    const int tr  = tid >> 2;
    const size_t row0 = (size_t)blockIdx.x * GR;

    float acc[4][12];
#pragma unroll
    for (int i = 0; i < 4; i++)
#pragma unroll
        for (int j = 0; j < 12; j++) acc[i][j] = 0.0f;

    for (int kc = 0; kc < DD; kc += GK) {
        const float4* wg = (const float4*)(w + (size_t)kc * UU);
        float4* wsv = (float4*)&ws[0][0];
#pragma unroll
        for (int i = 0; i < 6; i++) wsv[tid + i * 128] = wg[tid + i * 128];

#pragma unroll
        for (int i = 0; i < 16; i++) {
            int j  = tid + i * 128;
            int r  = j >> 4;
            int k4 = j & 15;
            float4 f = *(const float4*)(x + (row0 + (size_t)r) * DD + kc + k4 * 4);
            xs[k4 * 4 + 0][r] = f.x;
            xs[k4 * 4 + 1][r] = f.y;
            xs[k4 * 4 + 2][r] = f.z;
            xs[k4 * 4 + 3][r] = f.w;
        }
        __syncthreads();

#pragma unroll 4
        for (int k = 0; k < GK; k++) {
            float xv[4], wv[12];
            float2 xa = *(const float2*)&xs[k][tr * 4];
            float2 xb = *(const float2*)&xs[k][tr * 4 + 2];
            xv[0] = xa.x; xv[1] = xa.y; xv[2] = xb.x; xv[3] = xb.y;
#pragma unroll
            for (int q = 0; q < 3; q++) {
                float4 wq = *(const float4*)&ws[k][tc * 12 + q * 4];
                wv[q * 4 + 0] = wq.x; wv[q * 4 + 1] = wq.y;
                wv[q * 4 + 2] = wq.z; wv[q * 4 + 3] = wq.w;
            }
#pragma unroll
            for (int i = 0; i < 4; i++)
#pragma unroll
                for (int j = 0; j < 12; j++) acc[i][j] += xv[i] * wv[j];
        }
        __syncthreads();
    }

    float bv[12];
#pragma unroll
    for (int j = 0; j < 12; j++) bv[j] = bias[tc * 12 + j];

#pragma unroll
    for (int i = 0; i < 4; i++) {
        size_t r = row0 + tr * 4 + i;
        float* o = g_logits + r * UU + tc * 12;
#pragma unroll
        for (int j = 0; j < 12; j++) o[j] = acc[i][j] + bv[j];
    }
}

// ---------------------------------------------------------------------------
// Kernel 2: Viterbi forward, VALUE ONLY. One block per batch, 64 threads
// (48 active), 2 warps. Per step: pure-fmaxf max over 48 candidates, write
// the new state to smem double buffer AND stream the state row to g_st.
// No index work in the serial loop.
// ---------------------------------------------------------------------------
__global__ __launch_bounds__(64) void viterbi_fwd(const float* __restrict__ trans) {
    const int b   = blockIdx.x;
    const int tid = threadIdx.x;
    const bool act = tid < UU;
    const int u   = act ? tid : (UU - 1);

    __shared__ __align__(16) float st[2][UU];

    unsigned long long trv[24];
#pragma unroll
    for (int j = 0; j < 24; j++) {
        unsigned lo = __float_as_uint(trans[(2 * j) * UU + u]);
        unsigned hi = __float_as_uint(trans[(2 * j + 1) * UU + u]);
        trv[j] = (unsigned long long)lo | ((unsigned long long)hi << 32);
    }

    const float* lg = g_logits + (size_t)b * TT * UU + u;
    float* stout = g_st + (size_t)b * UU + u;
    if (act) {
        float s0 = lg[0];
        st[0][tid] = s0;
        stout[0] = s0;   // g_st row 0 = init state
    }

    float f0 = lg[(size_t)1 * UU];
    float f1 = lg[(size_t)2 * UU];
    float f2 = lg[(size_t)3 * UU];
    float f3 = lg[(size_t)4 * UU];
    __syncthreads();

    int p = 0;
    for (int t = 1; t < TT; ++t) {
        float cur = f0;
        f0 = f1;
        f1 = f2;
        f2 = f3;
        int tn = t + 4;
        if (tn > TT - 1) tn = TT - 1;
        f3 = lg[(size_t)tn * UU];

        float v[24];
#pragma unroll
        for (int m = 0; m < 12; m++) {
            ulonglong2 s = *(const ulonglong2*)&st[p][4 * m];
            unsigned long long ca, cb;
            ADD_F32X2(ca, s.x, trv[2 * m + 0]);
            ADD_F32X2(cb, s.y, trv[2 * m + 1]);
            float a0 = __uint_as_float((unsigned)(ca & 0xFFFFFFFFull));
            float a1 = __uint_as_float((unsigned)(ca >> 32));
            float b0 = __uint_as_float((unsigned)(cb & 0xFFFFFFFFull));
            float b1 = __uint_as_float((unsigned)(cb >> 32));
            v[2 * m + 0] = fmaxf(a0, a1);
            v[2 * m + 1] = fmaxf(b0, b1);
        }
#pragma unroll
        for (int j = 0; j < 12; j++) v[j] = fmaxf(v[2 * j], v[2 * j + 1]);
#pragma unroll
        for (int j = 0; j < 6; j++)  v[j] = fmaxf(v[2 * j], v[2 * j + 1]);
#pragma unroll
        for (int j = 0; j < 3; j++)  v[j] = fmaxf(v[2 * j], v[2 * j + 1]);
        float bv = fmaxf(fmaxf(v[0], v[1]), v[2]);

        float ns = cur + bv;
        if (act) {
            st[p ^ 1][tid] = ns;
            if (t <= TT - 2) stout[(size_t)t * BB * UU] = ns;  // state rows 1..1022
        }
        __syncthreads();
        p ^= 1;
    }

    if (tid == 0) {
        float bv = st[p][0];
        int bi = 0;
#pragma unroll
        for (int i = 1; i < UU; i++) {
            if (st[p][i] > bv) { bv = st[p][i]; bi = i; }
        }
        g_last[b] = bi;
    }
}

// ---------------------------------------------------------------------------
// Kernel 2b: backpointer extraction, fully parallel over (b, t, u).
// bp[t-1][b][u] = argmax_i(st[t-1][b][i] + trans[i][u]), first-index ties.
// Slot layout: reduction slot 2m covers candidates {4m, 4m+1}, slot 2m+1
// covers {4m+2, 4m+3}; slots ascend with candidate index, so strict-greater
// replacement at every node = first-index tie-break (matches jnp.argmax).
// Values computed with the identical add.rn.f32x2 / fmaxf sequence as fwd.
// ---------------------------------------------------------------------------
#define BP_T 4
#define TRP 50

__global__ __launch_bounds__(192) void bp_kernel(const float* __restrict__ trans) {
    __shared__ float trT[UU][TRP];                 // [u][i], padded
    __shared__ __align__(16) float sts[BP_T][UU];

    const int b   = blockIdx.x;
    const int t0  = blockIdx.y * BP_T + 1;         // first t handled
    const int tid = threadIdx.x;

    for (int idx = tid; idx < UU * UU; idx += 192) {
        int i = idx / UU;
        int uu = idx - i * UU;
        trT[uu][i] = trans[idx];
    }
    for (int idx = tid; idx < BP_T * UU; idx += 192) {
        int tl = idx / UU;
        int uu = idx - tl * UU;
        int s = t0 - 1 + tl;
        if (s <= TT - 2) sts[tl][uu] = g_st[(size_t)s * BB * UU + (size_t)b * UU + uu];
    }
    __syncthreads();

    const int tl = tid / UU;      // 0..3
    const int u  = tid - tl * UU; // 0..47
    const int t  = t0 + tl;
    if (t > TT - 1) return;

    float v[24];
    int   ix[24];
#pragma unroll
    for (int m = 0; m < 12; m++) {
        ulonglong2 s2 = *(const ulonglong2*)&sts[tl][4 * m];
        unsigned long long tr0 = *(const unsigned long long*)&trT[u][4 * m];
        unsigned long long tr1 = *(const unsigned long long*)&trT[u][4 * m + 2];
        unsigned long long ca, cb;
        ADD_F32X2(ca, s2.x, tr0);
        ADD_F32X2(cb, s2.y, tr1);
        float a0 = __uint_as_float((unsigned)(ca & 0xFFFFFFFFull));
        float a1 = __uint_as_float((unsigned)(ca >> 32));
        float b0 = __uint_as_float((unsigned)(cb & 0xFFFFFFFFull));
        float b1 = __uint_as_float((unsigned)(cb >> 32));
        v[2 * m + 0]  = fmaxf(a0, a1);
        ix[2 * m + 0] = (a1 > a0) ? (4 * m + 1) : (4 * m + 0);
        v[2 * m + 1]  = fmaxf(b0, b1);
        ix[2 * m + 1] = (b1 > b0) ? (4 * m + 3) : (4 * m + 2);
    }
#pragma unroll
    for (int j = 0; j < 12; j++) {
        bool g = v[2 * j + 1] > v[2 * j];
        v[j]  = fmaxf(v[2 * j], v[2 * j + 1]);
        ix[j] = g ? ix[2 * j + 1] : ix[2 * j];
    }
#pragma unroll
    for (int j = 0; j < 6; j++) {
        bool g = v[2 * j + 1] > v[2 * j];
        v[j]  = fmaxf(v[2 * j], v[2 * j + 1]);
        ix[j] = g ? ix[2 * j + 1] : ix[2 * j];
    }
#pragma unroll
    for (int j = 0; j < 3; j++) {
        bool g = v[2 * j + 1] > v[2 * j];
        v[j]  = fmaxf(v[2 * j], v[2 * j + 1]);
        ix[j] = g ? ix[2 * j + 1] : ix[2 * j];
    }
    float m01 = fmaxf(v[0], v[1]);
    int  i01  = (v[1] > v[0]) ? ix[1] : ix[0];
    int  bi   = (v[2] > m01) ? ix[2] : i01;

    g_bp[(size_t)(t - 1) * BB * UU + (size_t)b * UU + u] = (unsigned char)bi;
}

// ---------------------------------------------------------------------------
// Kernel 3: backtrack + emit. 128 blocks (one batch each), 256 threads.
// Stage bp column to SMEM, branchless LDS.U8 chain walk, float output.
// ---------------------------------------------------------------------------
__global__ __launch_bounds__(256) void backtrack_kernel(float* __restrict__ out) {
    __shared__ unsigned char sbp[(TT - 1) * UU];  // 49104 B

    const int b = blockIdx.x;
    const int tid = threadIdx.x;

    const unsigned char* gsrc = g_bp + (size_t)b * UU;
    for (int idx = tid; idx < (TT - 1) * 3; idx += 256) {
        int s = idx / 3;
        int w = idx % 3;
        uint4 v = *(const uint4*)(gsrc + (size_t)s * BB * UU + w * 16);
        *(uint4*)(sbp + s * UU + w * 16) = v;
    }
    __syncthreads();

    if (tid != 0) return;

    int tag = g_last[b];
    float* ob = out + (size_t)b * TT;
    ob[TT - 1] = (float)tag;

    int off = (TT - 2) * UU;
#pragma unroll 8
    for (int s = TT - 2; s >= 0; --s) {
        tag = sbp[off + tag];
        ob[s] = (float)tag;
        off -= UU;
    }
}

// ---------------------------------------------------------------------------
extern "C" void kernel_launch(void* const* d_in, const int* in_sizes, int n_in,
                              void* d_out, int out_size) {
    const float* x     = (const float*)d_in[0];  // (128,1024,256)
    const float* kern  = (const float*)d_in[1];  // (256,48)
    const float* bias  = (const float*)d_in[2];  // (48,)
    const float* chain = (const float*)d_in[3];  // (48,48)
    float* out = (float*)d_out;                  // (128,1024) float32

    gemm_kernel<<<(BB * TT) / GR, 128>>>(x, kern, bias);
    viterbi_fwd<<<BB, 64>>>(chain);
    bp_kernel<<<dim3(BB, (TT - 1 + BP_T - 1) / BP_T), 192>>>(chain);
    backtrack_kernel<<<BB, 256>>>(out);
}

// round 9
// speedup vs baseline: 1.5375x; 1.5375x over previous
#include <cuda_runtime.h>
#include <stdint.h>

#define BB 128
#define TT 1024
#define DD 256
#define UU 48

// Scratch (allocation-free rule: __device__ globals)
__device__ float         g_logits[(size_t)BB * TT * UU];     // 25.2 MB
__device__ unsigned char g_bp[(size_t)(TT - 1) * BB * UU];   // 6.29 MB
__device__ int           g_last[BB];

#define ADD_F32X2(out, a, b) \
    asm("add.rn.f32x2 %0, %1, %2;" : "=l"(out) : "l"(a), "l"(b))

// ---------------------------------------------------------------------------
// Kernel 1: logits = x @ kernel + bias (measured 105.5us ~ 1.12x fp32 floor)
// ---------------------------------------------------------------------------
#define GR 128
#define GK 64
#define XPAD 130

__global__ __launch_bounds__(128) void gemm_kernel(const float* __restrict__ x,
                                                   const float* __restrict__ w,
                                                   const float* __restrict__ bias) {
    __shared__ float xs[GK][XPAD];
    __shared__ float ws[GK][UU];

    const int tid = threadIdx.x;
    const int tc  = tid & 3;
    const int tr  = tid >> 2;
    const size_t row0 = (size_t)blockIdx.x * GR;

    float acc[4][12];
#pragma unroll
    for (int i = 0; i < 4; i++)
#pragma unroll
        for (int j = 0; j < 12; j++) acc[i][j] = 0.0f;

    for (int kc = 0; kc < DD; kc += GK) {
        const float4* wg = (const float4*)(w + (size_t)kc * UU);
        float4* wsv = (float4*)&ws[0][0];
#pragma unroll
        for (int i = 0; i < 6; i++) wsv[tid + i * 128] = wg[tid + i * 128];

#pragma unroll
        for (int i = 0; i < 16; i++) {
            int j  = tid + i * 128;
            int r  = j >> 4;
            int k4 = j & 15;
            float4 f = *(const float4*)(x + (row0 + (size_t)r) * DD + kc + k4 * 4);
            xs[k4 * 4 + 0][r] = f.x;
            xs[k4 * 4 + 1][r] = f.y;
            xs[k4 * 4 + 2][r] = f.z;
            xs[k4 * 4 + 3][r] = f.w;
        }
        __syncthreads();

#pragma unroll 4
        for (int k = 0; k < GK; k++) {
            float xv[4], wv[12];
            float2 xa = *(const float2*)&xs[k][tr * 4];
            float2 xb = *(const float2*)&xs[k][tr * 4 + 2];
            xv[0] = xa.x; xv[1] = xa.y; xv[2] = xb.x; xv[3] = xb.y;
#pragma unroll
            for (int q = 0; q < 3; q++) {
                float4 wq = *(const float4*)&ws[k][tc * 12 + q * 4];
                wv[q * 4 + 0] = wq.x; wv[q * 4 + 1] = wq.y;
                wv[q * 4 + 2] = wq.z; wv[q * 4 + 3] = wq.w;
            }
#pragma unroll
            for (int i = 0; i < 4; i++)
#pragma unroll
                for (int j = 0; j < 12; j++) acc[i][j] += xv[i] * wv[j];
        }
        __syncthreads();
    }

    float bv[12];
#pragma unroll
    for (int j = 0; j < 12; j++) bv[j] = bias[tc * 12 + j];

#pragma unroll
    for (int i = 0; i < 4; i++) {
        size_t r = row0 + tr * 4 + i;
        float* o = g_logits + r * UU + tc * 12;
#pragma unroll
        for (int j = 0; j < 12; j++) o[j] = acc[i][j] + bv[j];
    }
}

// ---------------------------------------------------------------------------
// Kernel 2: Viterbi forward, 4 warps = 1 warp per SMSP (fma rt_SMSP=2 is
// shared per SMSP; 5-warp layout double-loaded one SMSP -> ~560 cyc/step).
//   warps 0-1 (tid < 64, 48 active): VALUE recurrence, pure-fmaxf tree.
//   warps 2-3 (tid >= 64, 48 active): full 48-candidate argmax + bp store,
//     first-index tie-break (strict-greater, ascending-index slots).
// ---------------------------------------------------------------------------
__global__ __launch_bounds__(128) void viterbi_fwd(const float* __restrict__ trans) {
    const int b   = blockIdx.x;
    const int tid = threadIdx.x;

    __shared__ __align__(16) float st[2][UU];

    const bool is_val = (tid < 64);
    const int  lu     = is_val ? tid : (tid - 64);   // role-local output index
    const bool act    = (lu < UU);
    const int  u      = act ? lu : (UU - 1);

    // trans column u, packed into 24 f32x2 regs (both roles need it)
    unsigned long long trv[24];
#pragma unroll
    for (int j = 0; j < 24; j++) {
        unsigned lo = __float_as_uint(trans[(2 * j) * UU + u]);
        unsigned hi = __float_as_uint(trans[(2 * j + 1) * UU + u]);
        trv[j] = (unsigned long long)lo | ((unsigned long long)hi << 32);
    }

    // value threads own logits prefetch + state init
    const float* lg = g_logits + (size_t)b * TT * UU + u;
    float f0, f1, f2, f3;
    if (is_val) {
        if (act) st[0][lu] = lg[0];
        f0 = lg[(size_t)1 * UU];
        f1 = lg[(size_t)2 * UU];
        f2 = lg[(size_t)3 * UU];
        f3 = lg[(size_t)4 * UU];
    }
    unsigned char* bpb = g_bp + (size_t)b * UU + u;

    __syncthreads();

    int p = 0;
    for (int t = 1; t < TT; ++t) {
        if (is_val) {
            float cur = f0;
            f0 = f1;
            f1 = f2;
            f2 = f3;
            int tn = t + 4;
            if (tn > TT - 1) tn = TT - 1;
            f3 = lg[(size_t)tn * UU];

            float v[24];
#pragma unroll
            for (int m = 0; m < 12; m++) {
                ulonglong2 s = *(const ulonglong2*)&st[p][4 * m];
                unsigned long long ca, cb;
                ADD_F32X2(ca, s.x, trv[2 * m + 0]);
                ADD_F32X2(cb, s.y, trv[2 * m + 1]);
                float a0 = __uint_as_float((unsigned)(ca & 0xFFFFFFFFull));
                float a1 = __uint_as_float((unsigned)(ca >> 32));
                float b0 = __uint_as_float((unsigned)(cb & 0xFFFFFFFFull));
                float b1 = __uint_as_float((unsigned)(cb >> 32));
                v[2 * m + 0] = fmaxf(a0, a1);
                v[2 * m + 1] = fmaxf(b0, b1);
            }
#pragma unroll
            for (int j = 0; j < 12; j++) v[j] = fmaxf(v[2 * j], v[2 * j + 1]);
#pragma unroll
            for (int j = 0; j < 6; j++)  v[j] = fmaxf(v[2 * j], v[2 * j + 1]);
#pragma unroll
            for (int j = 0; j < 3; j++)  v[j] = fmaxf(v[2 * j], v[2 * j + 1]);
            float bv = fmaxf(fmaxf(v[0], v[1]), v[2]);

            if (act) st[p ^ 1][lu] = cur + bv;
        } else {
            // full 48-candidate argmax; slot j covers candidates {2j, 2j+1}
            float v[24];
            int   ix[24];
#pragma unroll
            for (int m = 0; m < 12; m++) {
                ulonglong2 s = *(const ulonglong2*)&st[p][4 * m];
                unsigned long long ca, cb;
                ADD_F32X2(ca, s.x, trv[2 * m + 0]);
                ADD_F32X2(cb, s.y, trv[2 * m + 1]);
                float a0 = __uint_as_float((unsigned)(ca & 0xFFFFFFFFull));
                float a1 = __uint_as_float((unsigned)(ca >> 32));
                float b0 = __uint_as_float((unsigned)(cb & 0xFFFFFFFFull));
                float b1 = __uint_as_float((unsigned)(cb >> 32));
                v[2 * m + 0]  = fmaxf(a0, a1);
                ix[2 * m + 0] = (a1 > a0) ? (4 * m + 1) : (4 * m + 0);
                v[2 * m + 1]  = fmaxf(b0, b1);
                ix[2 * m + 1] = (b1 > b0) ? (4 * m + 3) : (4 * m + 2);
            }
#pragma unroll
            for (int j = 0; j < 12; j++) {
                bool g = v[2 * j + 1] > v[2 * j];
                v[j]  = fmaxf(v[2 * j], v[2 * j + 1]);
                ix[j] = g ? ix[2 * j + 1] : ix[2 * j];
            }
#pragma unroll
            for (int j = 0; j < 6; j++) {
                bool g = v[2 * j + 1] > v[2 * j];
                v[j]  = fmaxf(v[2 * j], v[2 * j + 1]);
                ix[j] = g ? ix[2 * j + 1] : ix[2 * j];
            }
#pragma unroll
            for (int j = 0; j < 3; j++) {
                bool g = v[2 * j + 1] > v[2 * j];
                v[j]  = fmaxf(v[2 * j], v[2 * j + 1]);
                ix[j] = g ? ix[2 * j + 1] : ix[2 * j];
            }
            float m01 = fmaxf(v[0], v[1]);
            int  i01  = (v[1] > v[0]) ? ix[1] : ix[0];
            int  bi   = (v[2] > m01) ? ix[2] : i01;

            if (act) bpb[(size_t)(t - 1) * BB * UU] = (unsigned char)bi;
        }
        __syncthreads();
        p ^= 1;
    }

    if (tid == 0) {
        float bv = st[p][0];
        int bi = 0;
#pragma unroll
        for (int i = 1; i < UU; i++) {
            if (st[p][i] > bv) { bv = st[p][i]; bi = i; }
        }
        g_last[b] = bi;
    }
}

// ---------------------------------------------------------------------------
// Kernel 3: backtrack + emit (measured 29.5us). 128 blocks, 256 threads.
// Stage bp column to SMEM, branchless LDS.U8 chain walk, float output.
// ---------------------------------------------------------------------------
__global__ __launch_bounds__(256) void backtrack_kernel(float* __restrict__ out) {
    __shared__ unsigned char sbp[(TT - 1) * UU];  // 49104 B

    const int b = blockIdx.x;
    const int tid = threadIdx.x;

    const unsigned char* gsrc = g_bp + (size_t)b * UU;
    for (int idx = tid; idx < (TT - 1) * 3; idx += 256) {
        int s = idx / 3;
        int w = idx % 3;
        uint4 v = *(const uint4*)(gsrc + (size_t)s * BB * UU + w * 16);
        *(uint4*)(sbp + s * UU + w * 16) = v;
    }
    __syncthreads();

    if (tid != 0) return;

    int tag = g_last[b];
    float* ob = out + (size_t)b * TT;
    ob[TT - 1] = (float)tag;

    int off = (TT - 2) * UU;
#pragma unroll 8
    for (int s = TT - 2; s >= 0; --s) {
        tag = sbp[off + tag];
        ob[s] = (float)tag;
        off -= UU;
    }
}

// ---------------------------------------------------------------------------
extern "C" void kernel_launch(void* const* d_in, const int* in_sizes, int n_in,
                              void* d_out, int out_size) {
    const float* x     = (const float*)d_in[0];  // (128,1024,256)
    const float* kern  = (const float*)d_in[1];  // (256,48)
    const float* bias  = (const float*)d_in[2];  // (48,)
    const float* chain = (const float*)d_in[3];  // (48,48)
    float* out = (float*)d_out;                  // (128,1024) float32

    gemm_kernel<<<(BB * TT) / GR, 128>>>(x, kern, bias);
    viterbi_fwd<<<BB, 128>>>(chain);
    backtrack_kernel<<<BB, 256>>>(out);
}

// round 10
// speedup vs baseline: 1.9153x; 1.2457x over previous
#include <cuda_runtime.h>
#include <stdint.h>

#define BB 128
#define TT 1024
#define DD 256
#define UU 48

// Scratch (allocation-free rule: __device__ globals)
__device__ float         g_logits[(size_t)BB * TT * UU];     // 25.2 MB
__device__ unsigned char g_bp[(size_t)(TT - 1) * BB * UU];   // 6.29 MB
__device__ int           g_last[BB];

#define ADD_F32X2(out, a, b) \
    asm("add.rn.f32x2 %0, %1, %2;" : "=l"(out) : "l"(a), "l"(b))

// ---------------------------------------------------------------------------
// Kernel 1: logits = x @ kernel + bias (measured ~106us ~ 1.12x fp32 floor)
// ---------------------------------------------------------------------------
#define GR 128
#define GK 64
#define XPAD 130

__global__ __launch_bounds__(128) void gemm_kernel(const float* __restrict__ x,
                                                   const float* __restrict__ w,
                                                   const float* __restrict__ bias) {
    __shared__ float xs[GK][XPAD];
    __shared__ float ws[GK][UU];

    const int tid = threadIdx.x;
    const int tc  = tid & 3;
    const int tr  = tid >> 2;
    const size_t row0 = (size_t)blockIdx.x * GR;

    float acc[4][12];
#pragma unroll
    for (int i = 0; i < 4; i++)
#pragma unroll
        for (int j = 0; j < 12; j++) acc[i][j] = 0.0f;

    for (int kc = 0; kc < DD; kc += GK) {
        const float4* wg = (const float4*)(w + (size_t)kc * UU);
        float4* wsv = (float4*)&ws[0][0];
#pragma unroll
        for (int i = 0; i < 6; i++) wsv[tid + i * 128] = wg[tid + i * 128];

#pragma unroll
        for (int i = 0; i < 16; i++) {
            int j  = tid + i * 128;
            int r  = j >> 4;
            int k4 = j & 15;
            float4 f = *(const float4*)(x + (row0 + (size_t)r) * DD + kc + k4 * 4);
            xs[k4 * 4 + 0][r] = f.x;
            xs[k4 * 4 + 1][r] = f.y;
            xs[k4 * 4 + 2][r] = f.z;
            xs[k4 * 4 + 3][r] = f.w;
        }
        __syncthreads();

#pragma unroll 4
        for (int k = 0; k < GK; k++) {
            float xv[4], wv[12];
            float2 xa = *(const float2*)&xs[k][tr * 4];
            float2 xb = *(const float2*)&xs[k][tr * 4 + 2];
            xv[0] = xa.x; xv[1] = xa.y; xv[2] = xb.x; xv[3] = xb.y;
#pragma unroll
            for (int q = 0; q < 3; q++) {
                float4 wq = *(const float4*)&ws[k][tc * 12 + q * 4];
                wv[q * 4 + 0] = wq.x; wv[q * 4 + 1] = wq.y;
                wv[q * 4 + 2] = wq.z; wv[q * 4 + 3] = wq.w;
            }
#pragma unroll
            for (int i = 0; i < 4; i++)
#pragma unroll
                for (int j = 0; j < 12; j++) acc[i][j] += xv[i] * wv[j];
        }
        __syncthreads();
    }

    float bv[12];
#pragma unroll
    for (int j = 0; j < 12; j++) bv[j] = bias[tc * 12 + j];

#pragma unroll
    for (int i = 0; i < 4; i++) {
        size_t r = row0 + tr * 4 + i;
        float* o = g_logits + r * UU + tc * 12;
#pragma unroll
        for (int j = 0; j < 12; j++) o[j] = acc[i][j] + bv[j];
    }
}

// ---------------------------------------------------------------------------
// Forward step bodies (shared by main loop and epilogue).
// ---------------------------------------------------------------------------
__device__ __forceinline__ void value_step(const unsigned long long (&trv)[24],
                                           const float* __restrict__ stp,
                                           float* __restrict__ stn,
                                           int lu, bool act, float cur) {
    float v[24];
#pragma unroll
    for (int m = 0; m < 12; m++) {
        ulonglong2 s = *(const ulonglong2*)&stp[4 * m];
        unsigned long long ca, cb;
        ADD_F32X2(ca, s.x, trv[2 * m + 0]);
        ADD_F32X2(cb, s.y, trv[2 * m + 1]);
        float a0 = __uint_as_float((unsigned)(ca & 0xFFFFFFFFull));
        float a1 = __uint_as_float((unsigned)(ca >> 32));
        float b0 = __uint_as_float((unsigned)(cb & 0xFFFFFFFFull));
        float b1 = __uint_as_float((unsigned)(cb >> 32));
        v[2 * m + 0] = fmaxf(a0, a1);
        v[2 * m + 1] = fmaxf(b0, b1);
    }
#pragma unroll
    for (int j = 0; j < 12; j++) v[j] = fmaxf(v[2 * j], v[2 * j + 1]);
#pragma unroll
    for (int j = 0; j < 6; j++)  v[j] = fmaxf(v[2 * j], v[2 * j + 1]);
#pragma unroll
    for (int j = 0; j < 3; j++)  v[j] = fmaxf(v[2 * j], v[2 * j + 1]);
    float bv = fmaxf(fmaxf(v[0], v[1]), v[2]);
    if (act) stn[lu] = cur + bv;
}

// argmax over 48 candidates, first-index tie-break (strict-greater
// replacement, slots ascend with candidate index) — matches jnp.argmax.
__device__ __forceinline__ void index_step(const unsigned long long (&trv)[24],
                                           const float* __restrict__ stp,
                                           bool act, unsigned char* dst) {
    float v[24];
    int   ix[24];
#pragma unroll
    for (int m = 0; m < 12; m++) {
        ulonglong2 s = *(const ulonglong2*)&stp[4 * m];
        unsigned long long ca, cb;
        ADD_F32X2(ca, s.x, trv[2 * m + 0]);
        ADD_F32X2(cb, s.y, trv[2 * m + 1]);
        float a0 = __uint_as_float((unsigned)(ca & 0xFFFFFFFFull));
        float a1 = __uint_as_float((unsigned)(ca >> 32));
        float b0 = __uint_as_float((unsigned)(cb & 0xFFFFFFFFull));
        float b1 = __uint_as_float((unsigned)(cb >> 32));
        v[2 * m + 0]  = fmaxf(a0, a1);
        ix[2 * m + 0] = (a1 > a0) ? (4 * m + 1) : (4 * m + 0);
        v[2 * m + 1]  = fmaxf(b0, b1);
        ix[2 * m + 1] = (b1 > b0) ? (4 * m + 3) : (4 * m + 2);
    }
#pragma unroll
    for (int j = 0; j < 12; j++) {
        bool g = v[2 * j + 1] > v[2 * j];
        v[j]  = fmaxf(v[2 * j], v[2 * j + 1]);
        ix[j] = g ? ix[2 * j + 1] : ix[2 * j];
    }
#pragma unroll
    for (int j = 0; j < 6; j++) {
        bool g = v[2 * j + 1] > v[2 * j];
        v[j]  = fmaxf(v[2 * j], v[2 * j + 1]);
        ix[j] = g ? ix[2 * j + 1] : ix[2 * j];
    }
#pragma unroll
    for (int j = 0; j < 3; j++) {
        bool g = v[2 * j + 1] > v[2 * j];
        v[j]  = fmaxf(v[2 * j], v[2 * j + 1]);
        ix[j] = g ? ix[2 * j + 1] : ix[2 * j];
    }
    float m01 = fmaxf(v[0], v[1]);
    int  i01  = (v[1] > v[0]) ? ix[1] : ix[0];
    int  bi   = (v[2] > m01) ? ix[2] : i01;
    if (act) *dst = (unsigned char)bi;
}

// ---------------------------------------------------------------------------
// Kernel 2: Viterbi forward, 4 warps (1/SMSP):
//   warps 0-1 (48 active): VALUE recurrence (pure-fmaxf tree).
//   warps 2-3 (48 active): full argmax + bp store.
// t-loop unrolled x4 with statically-indexed prefetch regs fb[0..3]:
// each LDG is consumed 4 steps after issue -> L2 latency fully hidden
// (the old f0<-f1<-f2<-f3 shift exposed ~250 cyc/step on the MOV).
// ---------------------------------------------------------------------------
__global__ __launch_bounds__(128) void viterbi_fwd(const float* __restrict__ trans) {
    const int b   = blockIdx.x;
    const int tid = threadIdx.x;

    __shared__ __align__(16) float st[2][UU];

    const bool is_val = (tid < 64);
    const int  lu     = is_val ? tid : (tid - 64);
    const bool act    = (lu < UU);
    const int  u      = act ? lu : (UU - 1);

    unsigned long long trv[24];
#pragma unroll
    for (int j = 0; j < 24; j++) {
        unsigned lo = __float_as_uint(trans[(2 * j) * UU + u]);
        unsigned hi = __float_as_uint(trans[(2 * j + 1) * UU + u]);
        trv[j] = (unsigned long long)lo | ((unsigned long long)hi << 32);
    }

    const float* lg = g_logits + (size_t)b * TT * UU + u;
    float fb[4];
    if (is_val) {
        if (act) st[0][lu] = lg[0];
        fb[0] = lg[(size_t)1 * UU];
        fb[1] = lg[(size_t)2 * UU];
        fb[2] = lg[(size_t)3 * UU];
        fb[3] = lg[(size_t)4 * UU];
    }
    unsigned char* bpb = g_bp + (size_t)b * UU + u;

    __syncthreads();

    int p = 0;
    int tb = 1;
    for (; tb + 3 < TT; tb += 4) {
#pragma unroll
        for (int q = 0; q < 4; q++) {
            const int t = tb + q;
            if (is_val) {
                float cur = fb[q];
                int tn = t + 4;
                if (tn > TT - 1) tn = TT - 1;
                fb[q] = lg[(size_t)tn * UU];     // consumed 4 steps later
                value_step(trv, st[p], st[p ^ 1], lu, act, cur);
            } else {
                index_step(trv, st[p], act, bpb + (size_t)(t - 1) * BB * UU);
            }
            __syncthreads();
            p ^= 1;
        }
    }
    // epilogue: t = tb .. TT-1 (3 steps; fb[0..2] already hold their logits)
#pragma unroll
    for (int q = 0; q < 3; q++) {
        const int t = tb + q;
        if (t < TT) {
            if (is_val) {
                value_step(trv, st[p], st[p ^ 1], lu, act, fb[q]);
            } else {
                index_step(trv, st[p], act, bpb + (size_t)(t - 1) * BB * UU);
            }
            __syncthreads();
            p ^= 1;
        }
    }

    if (tid == 0) {
        float bv = st[p][0];
        int bi = 0;
#pragma unroll
        for (int i = 1; i < UU; i++) {
            if (st[p][i] > bv) { bv = st[p][i]; bi = i; }
        }
        g_last[b] = bi;
    }
}

// ---------------------------------------------------------------------------
// Kernel 3: backtrack + emit (measured 29.5us). 128 blocks, 256 threads.
// ---------------------------------------------------------------------------
__global__ __launch_bounds__(256) void backtrack_kernel(float* __restrict__ out) {
    __shared__ unsigned char sbp[(TT - 1) * UU];  // 49104 B

    const int b = blockIdx.x;
    const int tid = threadIdx.x;

    const unsigned char* gsrc = g_bp + (size_t)b * UU;
    for (int idx = tid; idx < (TT - 1) * 3; idx += 256) {
        int s = idx / 3;
        int w = idx % 3;
        uint4 v = *(const uint4*)(gsrc + (size_t)s * BB * UU + w * 16);
        *(uint4*)(sbp + s * UU + w * 16) = v;
    }
    __syncthreads();

    if (tid != 0) return;

    int tag = g_last[b];
    float* ob = out + (size_t)b * TT;
    ob[TT - 1] = (float)tag;

    int off = (TT - 2) * UU;
#pragma unroll 8
    for (int s = TT - 2; s >= 0; --s) {
        tag = sbp[off + tag];
        ob[s] = (float)tag;
        off -= UU;
    }
}

// ---------------------------------------------------------------------------
extern "C" void kernel_launch(void* const* d_in, const int* in_sizes, int n_in,
                              void* d_out, int out_size) {
    const float* x     = (const float*)d_in[0];  // (128,1024,256)
    const float* kern  = (const float*)d_in[1];  // (256,48)
    const float* bias  = (const float*)d_in[2];  // (48,)
    const float* chain = (const float*)d_in[3];  // (48,48)
    float* out = (float*)d_out;                  // (128,1024) float32

    gemm_kernel<<<(BB * TT) / GR, 128>>>(x, kern, bias);
    viterbi_fwd<<<BB, 128>>>(chain);
    backtrack_kernel<<<BB, 256>>>(out);
}